// round 1
// baseline (speedup 1.0000x reference)
#include <cuda_runtime.h>
#include <mma.h>

using namespace nvcuda;

#define BSZ 256
#define SLEN 64
#define HDIM 512
#define VDIM 32000
#define H2D 1024
#define NROWS (BSZ * SLEN) /* 16384 */

// ---------------- device scratch (static, no allocations) ----------------
__device__ float d_E[(size_t)NROWS * HDIM];        // embeddings, flat (B*S, H)
__device__ float d_Gf[(size_t)NROWS * 4 * HDIM];   // fwd input-gate preacts
__device__ float d_Gb[(size_t)NROWS * 4 * HDIM];   // bwd input-gate preacts
__device__ float d_CombIn[(size_t)NROWS * H2D];    // [hf | hb] per (t,b)
__device__ float d_Gc[(size_t)NROWS * 4 * H2D];    // combiner input-gate preacts
__device__ float d_h[2][2][BSZ * HDIM];            // [dir][parity]
__device__ float d_cfb[2][BSZ * HDIM];             // [dir]
__device__ float d_hcb[2][BSZ * H2D];              // combiner h [parity]
__device__ float d_cc[BSZ * H2D];

// round-to-nearest-even into tf32 (10 explicit mantissa bits)
__device__ __forceinline__ float t32(float x) {
    unsigned u = __float_as_uint(x);
    unsigned r = (u + 0xFFFu + ((u >> 13) & 1u)) & 0xFFFFE000u;
    return __uint_as_float(r);
}
__device__ __forceinline__ float sigm(float x) { return 1.f / (1.f + __expf(-x)); }

// ---------------- embedding gather (padding_idx = 0) ----------------
__global__ void embed_kernel(const int* __restrict__ x, const float* __restrict__ Wemb) {
    int r = blockIdx.x;
    int tok = x[r];
    float4* dst = (float4*)(d_E + (size_t)r * HDIM);
    if (tok == 0) {
        float4 z = {0.f, 0.f, 0.f, 0.f};
        dst[threadIdx.x] = z;
    } else {
        const float4* src = (const float4*)(Wemb + (size_t)tok * HDIM);
        dst[threadIdx.x] = src[threadIdx.x];
    }
}

// ---------------- generic TF32 GEMM: C[M,N] = A[M,K] @ W[N,K]^T ----------------
// block tile 128x128, BK=32, 256 threads (8 warps as 4x2, warp tile 32x64)
__global__ void __launch_bounds__(256) gemm_tf32(const float* __restrict__ A,
                                                 const float* __restrict__ W,
                                                 float* __restrict__ C,
                                                 int M, int N, int K) {
    __shared__ float As[128][36];
    __shared__ float Bs[128][36];
    const int m0 = blockIdx.y * 128, n0 = blockIdx.x * 128;
    const int tid = threadIdx.x;
    const int w = tid >> 5, wm = w >> 1, wn = w & 1;

    wmma::fragment<wmma::accumulator, 16, 16, 8, float> cf[2][4];
#pragma unroll
    for (int i = 0; i < 2; i++)
#pragma unroll
        for (int j = 0; j < 4; j++) wmma::fill_fragment(cf[i][j], 0.f);

    for (int k0 = 0; k0 < K; k0 += 32) {
#pragma unroll
        for (int i = 0; i < 4; i++) {
            int lin = tid + i * 256;
            int r = lin >> 3, c4 = (lin & 7) * 4;
            float4 v = *(const float4*)(A + (size_t)(m0 + r) * K + k0 + c4);
            v.x = t32(v.x); v.y = t32(v.y); v.z = t32(v.z); v.w = t32(v.w);
            *(float4*)(&As[r][c4]) = v;
        }
#pragma unroll
        for (int i = 0; i < 4; i++) {
            int lin = tid + i * 256;
            int r = lin >> 3, c4 = (lin & 7) * 4;
            float4 v = *(const float4*)(W + (size_t)(n0 + r) * K + k0 + c4);
            v.x = t32(v.x); v.y = t32(v.y); v.z = t32(v.z); v.w = t32(v.w);
            *(float4*)(&Bs[r][c4]) = v;
        }
        __syncthreads();
#pragma unroll
        for (int ks = 0; ks < 4; ks++) {
            wmma::fragment<wmma::matrix_a, 16, 16, 8, wmma::precision::tf32, wmma::row_major> af[2];
            wmma::fragment<wmma::matrix_b, 16, 16, 8, wmma::precision::tf32, wmma::col_major> bf[4];
#pragma unroll
            for (int i = 0; i < 2; i++) wmma::load_matrix_sync(af[i], &As[wm * 32 + i * 16][ks * 8], 36);
#pragma unroll
            for (int j = 0; j < 4; j++) wmma::load_matrix_sync(bf[j], &Bs[wn * 64 + j * 16][ks * 8], 36);
#pragma unroll
            for (int i = 0; i < 2; i++)
#pragma unroll
                for (int j = 0; j < 4; j++) wmma::mma_sync(cf[i][j], af[i], bf[j], cf[i][j]);
        }
        __syncthreads();
    }
#pragma unroll
    for (int i = 0; i < 2; i++)
#pragma unroll
        for (int j = 0; j < 4; j++)
            wmma::store_matrix_sync(C + (size_t)(m0 + wm * 32 + i * 16) * N + n0 + wn * 64 + j * 16,
                                    cf[i][j], N, wmma::mem_row_major);
}

// ---------------- fused LSTM step, fwd+bwd (grid.z = dir) ----------------
// block: 64 batch rows x 32 hidden cols (=> 128 gate cols). K=512.
__global__ void __launch_bounds__(256) lstm_step_fb(
    const float* __restrict__ WhhF, const float* __restrict__ WhhB,
    const float* __restrict__ biF, const float* __restrict__ bhF,
    const float* __restrict__ biB, const float* __restrict__ bhB, int t) {
    __shared__ float smbuf[8448];  // 33792 B: staging (As 2304 + Bs 4608 fl) / gbuf 64x132
    float(*As)[36] = (float(*)[36])smbuf;
    float(*Bs)[36] = (float(*)[36])(smbuf + 64 * 36);
    float(*gb)[132] = (float(*)[132])smbuf;

    const int dir = blockIdx.z;
    const float* Whh = dir ? WhhB : WhhF;
    const float* bi = dir ? biB : biF;
    const float* bh = dir ? bhB : bhF;
    const float* hprev = d_h[dir][t & 1];
    float* hnext = d_h[dir][(t + 1) & 1];
    float* cst = d_cfb[dir];
    const float* G = dir ? d_Gb : d_Gf;
    const int grow0 = (dir ? (SLEN - 1 - t) : t) * BSZ;

    const int m0 = blockIdx.x * 64;
    const int j0 = blockIdx.y * 32;
    const int tid = threadIdx.x;
    const int w = tid >> 5, wm = w >> 2, wn = w & 3;  // warp tile 32x32 over 64x128

    wmma::fragment<wmma::accumulator, 16, 16, 8, float> cf[2][2];
#pragma unroll
    for (int i = 0; i < 2; i++)
#pragma unroll
        for (int j = 0; j < 2; j++) wmma::fill_fragment(cf[i][j], 0.f);

    for (int k0 = 0; k0 < HDIM; k0 += 32) {
#pragma unroll
        for (int i = 0; i < 2; i++) {  // A: 64x32
            int lin = tid + i * 256;
            int r = lin >> 3, c4 = (lin & 7) * 4;
            float4 v = *(const float4*)(hprev + (size_t)(m0 + r) * HDIM + k0 + c4);
            v.x = t32(v.x); v.y = t32(v.y); v.z = t32(v.z); v.w = t32(v.w);
            *(float4*)(&As[r][c4]) = v;
        }
#pragma unroll
        for (int i = 0; i < 4; i++) {  // B: 128 gate rows x 32
            int lin = tid + i * 256;
            int r = lin >> 3, c4 = (lin & 7) * 4;
            int wrow = (r >> 5) * HDIM + j0 + (r & 31);
            float4 v = *(const float4*)(Whh + (size_t)wrow * HDIM + k0 + c4);
            v.x = t32(v.x); v.y = t32(v.y); v.z = t32(v.z); v.w = t32(v.w);
            *(float4*)(&Bs[r][c4]) = v;
        }
        __syncthreads();
#pragma unroll
        for (int ks = 0; ks < 4; ks++) {
            wmma::fragment<wmma::matrix_a, 16, 16, 8, wmma::precision::tf32, wmma::row_major> af[2];
            wmma::fragment<wmma::matrix_b, 16, 16, 8, wmma::precision::tf32, wmma::col_major> bf[2];
#pragma unroll
            for (int i = 0; i < 2; i++) wmma::load_matrix_sync(af[i], &As[wm * 32 + i * 16][ks * 8], 36);
#pragma unroll
            for (int j = 0; j < 2; j++) wmma::load_matrix_sync(bf[j], &Bs[wn * 32 + j * 16][ks * 8], 36);
#pragma unroll
            for (int i = 0; i < 2; i++)
#pragma unroll
                for (int j = 0; j < 2; j++) wmma::mma_sync(cf[i][j], af[i], bf[j], cf[i][j]);
        }
        __syncthreads();
    }
#pragma unroll
    for (int i = 0; i < 2; i++)
#pragma unroll
        for (int j = 0; j < 2; j++)
            wmma::store_matrix_sync(&gb[wm * 32 + i * 16][wn * 32 + j * 16], cf[i][j], 132,
                                    wmma::mem_row_major);
    __syncthreads();

#pragma unroll
    for (int p = 0; p < 8; p++) {  // 64x32 cell elements
        int idx = p * 256 + tid;
        int m = idx >> 5, jj = idx & 31;
        int b = m0 + m, j = j0 + jj;
        const float* grow = G + (size_t)(grow0 + b) * (4 * HDIM);
        float ip = gb[m][jj]      + grow[j]            + bi[j]            + bh[j];
        float fp = gb[m][32 + jj] + grow[HDIM + j]     + bi[HDIM + j]     + bh[HDIM + j];
        float gp = gb[m][64 + jj] + grow[2 * HDIM + j] + bi[2 * HDIM + j] + bh[2 * HDIM + j];
        float op = gb[m][96 + jj] + grow[3 * HDIM + j] + bi[3 * HDIM + j] + bh[3 * HDIM + j];
        float cn = sigm(fp) * cst[b * HDIM + j] + sigm(ip) * tanhf(gp);
        cst[b * HDIM + j] = cn;
        float hn = sigm(op) * tanhf(cn);
        hnext[b * HDIM + j] = hn;
        d_CombIn[(size_t)(t * BSZ + b) * H2D + dir * HDIM + j] = hn;
    }
}

// ---------------- fused combiner LSTM step (H=1024) ----------------
__global__ void __launch_bounds__(256) lstm_step_c(
    const float* __restrict__ Whh, const float* __restrict__ bi,
    const float* __restrict__ bh, int t) {
    __shared__ float smbuf[8448];
    float(*As)[36] = (float(*)[36])smbuf;
    float(*Bs)[36] = (float(*)[36])(smbuf + 64 * 36);
    float(*gb)[132] = (float(*)[132])smbuf;

    const float* hprev = d_hcb[t & 1];
    float* hnext = d_hcb[(t + 1) & 1];
    float* cst = d_cc;
    const int grow0 = t * BSZ;

    const int m0 = blockIdx.x * 64;
    const int j0 = blockIdx.y * 32;
    const int tid = threadIdx.x;
    const int w = tid >> 5, wm = w >> 2, wn = w & 3;

    wmma::fragment<wmma::accumulator, 16, 16, 8, float> cf[2][2];
#pragma unroll
    for (int i = 0; i < 2; i++)
#pragma unroll
        for (int j = 0; j < 2; j++) wmma::fill_fragment(cf[i][j], 0.f);

    for (int k0 = 0; k0 < H2D; k0 += 32) {
#pragma unroll
        for (int i = 0; i < 2; i++) {
            int lin = tid + i * 256;
            int r = lin >> 3, c4 = (lin & 7) * 4;
            float4 v = *(const float4*)(hprev + (size_t)(m0 + r) * H2D + k0 + c4);
            v.x = t32(v.x); v.y = t32(v.y); v.z = t32(v.z); v.w = t32(v.w);
            *(float4*)(&As[r][c4]) = v;
        }
#pragma unroll
        for (int i = 0; i < 4; i++) {
            int lin = tid + i * 256;
            int r = lin >> 3, c4 = (lin & 7) * 4;
            int wrow = (r >> 5) * H2D + j0 + (r & 31);
            float4 v = *(const float4*)(Whh + (size_t)wrow * H2D + k0 + c4);
            v.x = t32(v.x); v.y = t32(v.y); v.z = t32(v.z); v.w = t32(v.w);
            *(float4*)(&Bs[r][c4]) = v;
        }
        __syncthreads();
#pragma unroll
        for (int ks = 0; ks < 4; ks++) {
            wmma::fragment<wmma::matrix_a, 16, 16, 8, wmma::precision::tf32, wmma::row_major> af[2];
            wmma::fragment<wmma::matrix_b, 16, 16, 8, wmma::precision::tf32, wmma::col_major> bf[2];
#pragma unroll
            for (int i = 0; i < 2; i++) wmma::load_matrix_sync(af[i], &As[wm * 32 + i * 16][ks * 8], 36);
#pragma unroll
            for (int j = 0; j < 2; j++) wmma::load_matrix_sync(bf[j], &Bs[wn * 32 + j * 16][ks * 8], 36);
#pragma unroll
            for (int i = 0; i < 2; i++)
#pragma unroll
                for (int j = 0; j < 2; j++) wmma::mma_sync(cf[i][j], af[i], bf[j], cf[i][j]);
        }
        __syncthreads();
    }
#pragma unroll
    for (int i = 0; i < 2; i++)
#pragma unroll
        for (int j = 0; j < 2; j++)
            wmma::store_matrix_sync(&gb[wm * 32 + i * 16][wn * 32 + j * 16], cf[i][j], 132,
                                    wmma::mem_row_major);
    __syncthreads();

#pragma unroll
    for (int p = 0; p < 8; p++) {
        int idx = p * 256 + tid;
        int m = idx >> 5, jj = idx & 31;
        int b = m0 + m, j = j0 + jj;
        const float* grow = d_Gc + (size_t)(grow0 + b) * (4 * H2D);
        float ip = gb[m][jj]      + grow[j]           + bi[j]           + bh[j];
        float fp = gb[m][32 + jj] + grow[H2D + j]     + bi[H2D + j]     + bh[H2D + j];
        float gp = gb[m][64 + jj] + grow[2 * H2D + j] + bi[2 * H2D + j] + bh[2 * H2D + j];
        float op = gb[m][96 + jj] + grow[3 * H2D + j] + bi[3 * H2D + j] + bh[3 * H2D + j];
        float cn = sigm(fp) * cst[b * H2D + j] + sigm(ip) * tanhf(gp);
        cst[b * H2D + j] = cn;
        hnext[b * H2D + j] = sigm(op) * tanhf(cn);
    }
}

// ---------------- head: 3xTF32 error-compensated GEMM (fp32-accurate) ----------------
__global__ void __launch_bounds__(256) head3_kernel(const float* __restrict__ A,
                                                    const float* __restrict__ W,
                                                    float* __restrict__ C) {
    extern __shared__ float sm[];
    float(*Ahi)[36] = (float(*)[36])sm;
    float(*Alo)[36] = (float(*)[36])(sm + 128 * 36);
    float(*Bhi)[36] = (float(*)[36])(sm + 2 * 128 * 36);
    float(*Blo)[36] = (float(*)[36])(sm + 3 * 128 * 36);
    const int K = H2D, N = VDIM;
    const int m0 = blockIdx.y * 128, n0 = blockIdx.x * 128;
    const int tid = threadIdx.x;
    const int w = tid >> 5, wm = w >> 1, wn = w & 1;

    wmma::fragment<wmma::accumulator, 16, 16, 8, float> cf[2][4];
#pragma unroll
    for (int i = 0; i < 2; i++)
#pragma unroll
        for (int j = 0; j < 4; j++) wmma::fill_fragment(cf[i][j], 0.f);

    for (int k0 = 0; k0 < K; k0 += 32) {
#pragma unroll
        for (int i = 0; i < 4; i++) {
            int lin = tid + i * 256;
            int r = lin >> 3, c4 = (lin & 7) * 4;
            float4 v = *(const float4*)(A + (size_t)(m0 + r) * K + k0 + c4);
            float4 hi, lo;
            hi.x = t32(v.x); lo.x = t32(v.x - hi.x);
            hi.y = t32(v.y); lo.y = t32(v.y - hi.y);
            hi.z = t32(v.z); lo.z = t32(v.z - hi.z);
            hi.w = t32(v.w); lo.w = t32(v.w - hi.w);
            *(float4*)(&Ahi[r][c4]) = hi;
            *(float4*)(&Alo[r][c4]) = lo;
        }
#pragma unroll
        for (int i = 0; i < 4; i++) {
            int lin = tid + i * 256;
            int r = lin >> 3, c4 = (lin & 7) * 4;
            float4 v = *(const float4*)(W + (size_t)(n0 + r) * K + k0 + c4);
            float4 hi, lo;
            hi.x = t32(v.x); lo.x = t32(v.x - hi.x);
            hi.y = t32(v.y); lo.y = t32(v.y - hi.y);
            hi.z = t32(v.z); lo.z = t32(v.z - hi.z);
            hi.w = t32(v.w); lo.w = t32(v.w - hi.w);
            *(float4*)(&Bhi[r][c4]) = hi;
            *(float4*)(&Blo[r][c4]) = lo;
        }
        __syncthreads();
#pragma unroll
        for (int ks = 0; ks < 4; ks++) {
            wmma::fragment<wmma::matrix_a, 16, 16, 8, wmma::precision::tf32, wmma::row_major> ah[2], al[2];
            wmma::fragment<wmma::matrix_b, 16, 16, 8, wmma::precision::tf32, wmma::col_major> bhf[4], blf[4];
#pragma unroll
            for (int i = 0; i < 2; i++) {
                wmma::load_matrix_sync(ah[i], &Ahi[wm * 32 + i * 16][ks * 8], 36);
                wmma::load_matrix_sync(al[i], &Alo[wm * 32 + i * 16][ks * 8], 36);
            }
#pragma unroll
            for (int j = 0; j < 4; j++) {
                wmma::load_matrix_sync(bhf[j], &Bhi[wn * 64 + j * 16][ks * 8], 36);
                wmma::load_matrix_sync(blf[j], &Blo[wn * 64 + j * 16][ks * 8], 36);
            }
#pragma unroll
            for (int i = 0; i < 2; i++)
#pragma unroll
                for (int j = 0; j < 4; j++) {
                    wmma::mma_sync(cf[i][j], al[i], bhf[j], cf[i][j]);
                    wmma::mma_sync(cf[i][j], ah[i], blf[j], cf[i][j]);
                    wmma::mma_sync(cf[i][j], ah[i], bhf[j], cf[i][j]);
                }
        }
        __syncthreads();
    }
#pragma unroll
    for (int i = 0; i < 2; i++)
#pragma unroll
        for (int j = 0; j < 4; j++)
            wmma::store_matrix_sync(C + (size_t)(m0 + wm * 32 + i * 16) * N + n0 + wn * 64 + j * 16,
                                    cf[i][j], N, wmma::mem_row_major);
}

__global__ void bias_add_kernel(float* __restrict__ C, const float* __restrict__ bout) {
    size_t idx = (size_t)blockIdx.x * 256 + threadIdx.x;  // float4 index over 256*32000
    float4 v = ((float4*)C)[idx];
    int n = (int)(idx % (VDIM / 4)) * 4;
    v.x += bout[n]; v.y += bout[n + 1]; v.z += bout[n + 2]; v.w += bout[n + 3];
    ((float4*)C)[idx] = v;
}

// ---------------- host orchestration ----------------
extern "C" void kernel_launch(void* const* d_in, const int* in_sizes, int n_in,
                              void* d_out, int out_size) {
    (void)in_sizes; (void)n_in; (void)out_size;
    const int* x = (const int*)d_in[0];
    const float* Wemb = (const float*)d_in[1];
    const float* WihF = (const float*)d_in[2];
    const float* WhhF = (const float*)d_in[3];
    const float* biF = (const float*)d_in[4];
    const float* bhF = (const float*)d_in[5];
    const float* WihB = (const float*)d_in[6];
    const float* WhhB = (const float*)d_in[7];
    const float* biB = (const float*)d_in[8];
    const float* bhB = (const float*)d_in[9];
    const float* WihC = (const float*)d_in[10];
    const float* WhhC = (const float*)d_in[11];
    const float* biC = (const float*)d_in[12];
    const float* bhC = (const float*)d_in[13];
    const float* Wout = (const float*)d_in[14];
    const float* bout = (const float*)d_in[15];
    const float* h0f = (const float*)d_in[16];
    const float* c0f = (const float*)d_in[17];
    const float* h0b = (const float*)d_in[18];
    const float* c0b = (const float*)d_in[19];
    const float* h0c = (const float*)d_in[20];
    const float* c0c = (const float*)d_in[21];
    float* out = (float*)d_out;

    void *pE, *pGf, *pGb, *pCI, *pGc, *ph, *pc, *phc, *pcc;
    cudaGetSymbolAddress(&pE, d_E);
    cudaGetSymbolAddress(&pGf, d_Gf);
    cudaGetSymbolAddress(&pGb, d_Gb);
    cudaGetSymbolAddress(&pCI, d_CombIn);
    cudaGetSymbolAddress(&pGc, d_Gc);
    cudaGetSymbolAddress(&ph, d_h);
    cudaGetSymbolAddress(&pc, d_cfb);
    cudaGetSymbolAddress(&phc, d_hcb);
    cudaGetSymbolAddress(&pcc, d_cc);

    cudaFuncSetAttribute(head3_kernel, cudaFuncAttributeMaxDynamicSharedMemorySize, 4 * 128 * 36 * 4);

    const size_t HS = (size_t)BSZ * HDIM * sizeof(float);
    const size_t H2S = (size_t)BSZ * H2D * sizeof(float);
    cudaMemcpyAsync(ph, h0f, HS, cudaMemcpyDeviceToDevice, 0);                   // d_h[0][0]
    cudaMemcpyAsync((char*)ph + 2 * HS, h0b, HS, cudaMemcpyDeviceToDevice, 0);   // d_h[1][0]
    cudaMemcpyAsync(pc, c0f, HS, cudaMemcpyDeviceToDevice, 0);
    cudaMemcpyAsync((char*)pc + HS, c0b, HS, cudaMemcpyDeviceToDevice, 0);
    cudaMemcpyAsync(phc, h0c, H2S, cudaMemcpyDeviceToDevice, 0);                 // d_hcb[0]
    cudaMemcpyAsync(pcc, c0c, H2S, cudaMemcpyDeviceToDevice, 0);

    embed_kernel<<<NROWS, 128>>>(x, Wemb);
    // input projections (biases folded in at the step kernels)
    gemm_tf32<<<dim3((4 * HDIM) / 128, NROWS / 128), 256>>>((const float*)pE, WihF, (float*)pGf,
                                                            NROWS, 4 * HDIM, HDIM);
    gemm_tf32<<<dim3((4 * HDIM) / 128, NROWS / 128), 256>>>((const float*)pE, WihB, (float*)pGb,
                                                            NROWS, 4 * HDIM, HDIM);
    // fwd + bwd recurrence (fused per step)
    for (int t = 0; t < SLEN; t++)
        lstm_step_fb<<<dim3(BSZ / 64, HDIM / 32, 2), 256>>>(WhhF, WhhB, biF, bhF, biB, bhB, t);
    // combiner input projection over all timesteps, then combiner recurrence
    gemm_tf32<<<dim3((4 * H2D) / 128, NROWS / 128), 256>>>((const float*)pCI, WihC, (float*)pGc,
                                                           NROWS, 4 * H2D, H2D);
    for (int t = 0; t < SLEN; t++)
        lstm_step_c<<<dim3(BSZ / 64, H2D / 32), 256>>>(WhhC, biC, bhC, t);
    // output head (3xTF32) + bias
    head3_kernel<<<dim3(VDIM / 128, BSZ / 128), 256, 4 * 128 * 36 * 4>>>((const float*)phc, Wout, out);
    bias_add_kernel<<<(BSZ * VDIM / 4) / 256, 256>>>(out, bout);
}